// round 6
// baseline (speedup 1.0000x reference)
#include <cuda_runtime.h>
#include <cuda_bf16.h>

#define N_NODES 50000
#define N_EDGES_MAX 600000
#define D 128
#define N_CLASSES 40

#define SCAN_BLK 1024
#define SCAN_NBLK ((N_NODES + SCAN_BLK - 1) / SCAN_BLK)   // 49

// Scratch (static device globals — no allocations allowed).
// Only referenced from DEVICE code (host shadow deref is silent on GB300/ATS).
__device__ float g_buf0[N_NODES * D];  // layer activations ping
__device__ float g_buf1[N_NODES * D];  // layer activations pong
__device__ int   g_cnt[N_NODES];       // in-degree histogram
__device__ int   g_row[N_NODES + 1];   // CSR row pointers (by dst)
__device__ int   g_cur[N_NODES];       // fill cursors
__device__ int   g_esrc[N_EDGES_MAX];  // CSR column indices (src nodes)
__device__ int   g_bsum[SCAN_NBLK];    // per-block scan totals

// ---------------------------------------------------------------------------
// CSR build
// ---------------------------------------------------------------------------
__global__ void gcn_zero_cnt_kernel() {
    int i = blockIdx.x * blockDim.x + threadIdx.x;
    if (i < N_NODES) g_cnt[i] = 0;
}

__global__ void gcn_hist_kernel(const int* __restrict__ dst, int n_edges) {
    int e = blockIdx.x * blockDim.x + threadIdx.x;
    if (e < n_edges) atomicAdd(&g_cnt[dst[e]], 1);
}

__global__ void gcn_scanA_kernel() {
    __shared__ int sh[SCAN_BLK];
    int t = threadIdx.x;
    int idx = blockIdx.x * SCAN_BLK + t;
    int v = (idx < N_NODES) ? g_cnt[idx] : 0;
    sh[t] = v;
    __syncthreads();
    for (int off = 1; off < SCAN_BLK; off <<= 1) {
        int u = (t >= off) ? sh[t - off] : 0;
        __syncthreads();
        sh[t] += u;
        __syncthreads();
    }
    if (idx < N_NODES) g_row[idx] = sh[t] - v;
    if (t == SCAN_BLK - 1) g_bsum[blockIdx.x] = sh[t];
}

__global__ void gcn_scanB_kernel() {
    int t = threadIdx.x;
    int blk = blockIdx.x;
    int off = 0;
    for (int b = 0; b < blk; b++) off += g_bsum[b];
    int idx = blk * SCAN_BLK + t;
    if (idx < N_NODES) {
        int r = g_row[idx] + off;
        g_row[idx] = r;
        g_cur[idx] = r;
        if (idx == N_NODES - 1) g_row[N_NODES] = r + g_cnt[idx];
    }
}

__global__ void gcn_fill_kernel(const int* __restrict__ src,
                                const int* __restrict__ dst, int n_edges) {
    int e = blockIdx.x * blockDim.x + threadIdx.x;
    if (e < n_edges) {
        int pos = atomicAdd(&g_cur[dst[e]], 1);
        g_esrc[pos] = src[e];
    }
}

// ---------------------------------------------------------------------------
// Input/output selection by template (device-symbol addresses stay device-side)
// INSEL: 0 = param pointer (x), 1 = g_buf0, 2 = g_buf1
// ---------------------------------------------------------------------------
template <int SEL>
__device__ __forceinline__ const float* sel_in(const float* p) {
    if (SEL == 0) return p;
    if (SEL == 1) return g_buf0;
    return g_buf1;
}
template <int SEL>
__device__ __forceinline__ float* sel_out(float* p) {
    if (SEL == 0) return p;
    if (SEL == 1) return g_buf0;
    return g_buf1;
}

// ---------------------------------------------------------------------------
// Fused GCN layer: block = 64 nodes.
//  Phase 1: load W into smem (Bs, transposed) — all 256 threads.
//  Phase 2: 8 warps gather 8 node rows each: acc = in[n] + sum in[nbr],
//           written straight into the As smem tile (no global round-trip).
//  Phase 3: FFMA2 GEMM As x Bs -> out rows (bias + optional ReLU).
// ---------------------------------------------------------------------------
template <int INSEL, int OUTSEL, int BN, int TNP, bool RELU>
__global__ void gcn_fused_kernel(const float* __restrict__ in_p,
                                 const float* __restrict__ W,
                                 const float* __restrict__ bias,
                                 float* __restrict__ out_p,
                                 int n_out, int ldo) {
    constexpr int BM = 64;
    constexpr int K = D;
    constexpr int LDA = K + 4;    // 132 (row stride 528B, 16B-aligned)
    constexpr int LDB = BN + 8;   // even pad for 8B pair loads
    extern __shared__ float sm[];
    float* As = sm;               // [BM][LDA]
    float* Bs = sm + BM * LDA;    // [K][LDB]

    const float* in = sel_in<INSEL>(in_p);
    int tid = threadIdx.x;
    int wid = tid >> 5;
    int lane = tid & 31;
    int row0 = blockIdx.x * BM;

    // Phase 1: W -> Bs (transposed)
    for (int i = tid; i < BN * K; i += 256) {
        int j = i / K, k = i % K;
        float v = (j < n_out) ? __ldg(W + j * K + k) : 0.f;
        Bs[k * LDB + j] = v;
    }

    // Phase 2: gather 8 rows per warp into As
#pragma unroll 1
    for (int q = 0; q < 8; q++) {
        int r = wid * 8 + q;
        int node = row0 + r;
        if (node >= N_NODES) break;
        int beg = g_row[node];
        int end = g_row[node + 1];
        float4 acc = *(const float4*)(in + (size_t)node * D + lane * 4);  // self
        int i = beg;
        for (; i + 4 <= end; i += 4) {
            int s0 = g_esrc[i], s1 = g_esrc[i + 1];
            int s2 = g_esrc[i + 2], s3 = g_esrc[i + 3];
            float4 v0 = *(const float4*)(in + (size_t)s0 * D + lane * 4);
            float4 v1 = *(const float4*)(in + (size_t)s1 * D + lane * 4);
            float4 v2 = *(const float4*)(in + (size_t)s2 * D + lane * 4);
            float4 v3 = *(const float4*)(in + (size_t)s3 * D + lane * 4);
            acc.x += v0.x + v1.x + v2.x + v3.x;
            acc.y += v0.y + v1.y + v2.y + v3.y;
            acc.z += v0.z + v1.z + v2.z + v3.z;
            acc.w += v0.w + v1.w + v2.w + v3.w;
        }
        for (; i < end; i++) {
            int s = g_esrc[i];
            float4 v = *(const float4*)(in + (size_t)s * D + lane * 4);
            acc.x += v.x; acc.y += v.y; acc.z += v.z; acc.w += v.w;
        }
        *(float4*)(As + r * LDA + lane * 4) = acc;
    }
    __syncthreads();

    // Phase 3: FFMA2 GEMM
    int tc = tid & 15;
    int tr = tid >> 4;

    unsigned long long acc[4][TNP];
#pragma unroll
    for (int ii = 0; ii < 4; ii++)
#pragma unroll
        for (int jj = 0; jj < TNP; jj++) acc[ii][jj] = 0ULL;

#pragma unroll 4
    for (int k = 0; k < K; k++) {
        unsigned long long ap[4], bp[TNP];
#pragma unroll
        for (int ii = 0; ii < 4; ii++) {
            float a = As[(tr * 4 + ii) * LDA + k];
            asm("mov.b64 %0, {%1, %2};" : "=l"(ap[ii]) : "f"(a), "f"(a));
        }
#pragma unroll
        for (int jj = 0; jj < TNP; jj++)
            bp[jj] = *(const unsigned long long*)(Bs + k * LDB + 2 * tc + 32 * jj);
#pragma unroll
        for (int ii = 0; ii < 4; ii++)
#pragma unroll
            for (int jj = 0; jj < TNP; jj++)
                asm("fma.rn.f32x2 %0, %1, %2, %0;"
                    : "+l"(acc[ii][jj]) : "l"(ap[ii]), "l"(bp[jj]));
    }

    float* outp = sel_out<OUTSEL>(out_p);
#pragma unroll
    for (int ii = 0; ii < 4; ii++) {
        int g = row0 + tr * 4 + ii;
        if (g >= N_NODES) continue;
#pragma unroll
        for (int jj = 0; jj < TNP; jj++) {
            int j0 = 2 * tc + 32 * jj;
            float lo, hi;
            asm("mov.b64 {%0, %1}, %2;" : "=f"(lo), "=f"(hi) : "l"(acc[ii][jj]));
            if (j0 < n_out) {
                float v = lo + __ldg(bias + j0);
                if (RELU) v = fmaxf(v, 0.f);
                outp[(size_t)g * ldo + j0] = v;
            }
            if (j0 + 1 < n_out) {
                float v = hi + __ldg(bias + j0 + 1);
                if (RELU) v = fmaxf(v, 0.f);
                outp[(size_t)g * ldo + j0 + 1] = v;
            }
        }
    }
}

// ---------------------------------------------------------------------------
extern "C" void kernel_launch(void* const* d_in, const int* in_sizes, int n_in,
                              void* d_out, int out_size) {
    const float* x  = (const float*)d_in[0];
    const int* src  = (const int*)d_in[1];
    const int* dst  = (const int*)d_in[2];
    const float* W0 = (const float*)d_in[3];
    const float* b0 = (const float*)d_in[4];
    const float* W1 = (const float*)d_in[5];
    const float* b1 = (const float*)d_in[6];
    const float* W2 = (const float*)d_in[7];
    const float* b2 = (const float*)d_in[8];
    float* out = (float*)d_out;
    int n_edges = in_sizes[1];

    constexpr int SMEM_BIG   = (64 * 132 + 128 * 136) * 4;  // 103424 B
    constexpr int SMEM_SMALL = (64 * 132 + 128 * 72) * 4;   //  70656 B
    static bool attr_done = false;
    if (!attr_done) {
        cudaFuncSetAttribute(gcn_fused_kernel<0, 1, 128, 4, true>,
                             cudaFuncAttributeMaxDynamicSharedMemorySize, SMEM_BIG);
        cudaFuncSetAttribute(gcn_fused_kernel<1, 2, 128, 4, true>,
                             cudaFuncAttributeMaxDynamicSharedMemorySize, SMEM_BIG);
        cudaFuncSetAttribute(gcn_fused_kernel<2, 0, 64, 2, false>,
                             cudaFuncAttributeMaxDynamicSharedMemorySize, SMEM_SMALL);
        attr_done = true;
    }

    int node_blocks = (N_NODES + 255) / 256;
    int edge_blocks = (n_edges + 255) / 256;
    int fuse_blocks = (N_NODES + 63) / 64;

    // CSR build (once per launch)
    gcn_zero_cnt_kernel<<<node_blocks, 256>>>();
    gcn_hist_kernel<<<edge_blocks, 256>>>(dst, n_edges);
    gcn_scanA_kernel<<<SCAN_NBLK, SCAN_BLK>>>();
    gcn_scanB_kernel<<<SCAN_NBLK, SCAN_BLK>>>();
    gcn_fill_kernel<<<edge_blocks, 256>>>(src, dst, n_edges);

    // Layer 0: x -> g_buf0
    gcn_fused_kernel<0, 1, 128, 4, true><<<fuse_blocks, 256, SMEM_BIG>>>(
        x, W0, b0, nullptr, D, D);
    // Layer 1: g_buf0 -> g_buf1
    gcn_fused_kernel<1, 2, 128, 4, true><<<fuse_blocks, 256, SMEM_BIG>>>(
        nullptr, W1, b1, nullptr, D, D);
    // Layer 2 (head): g_buf1 -> out
    gcn_fused_kernel<2, 0, 64, 2, false><<<fuse_blocks, 256, SMEM_SMALL>>>(
        nullptr, W2, b2, out, N_CLASSES, N_CLASSES);
}